// round 2
// baseline (speedup 1.0000x reference)
#include <cuda_runtime.h>

#define B_  4
#define L_  100
#define BL_ 400           // B*L
#define DM_ 128           // d_model
#define DI_ 256           // d_inner
#define DS_ 256           // d_state

// scratch (device globals; no allocations allowed)
__device__ float g_xpre[BL_ * DI_];
__device__ float g_x   [BL_ * DI_];
__device__ float g_z   [BL_ * DI_];
__device__ float g_Bm  [BL_ * DS_];
__device__ float g_dt  [BL_ * DI_];
__device__ float g_y   [BL_ * DI_];
__device__ float g_negA[DI_ * DS_];

// ---------------------------------------------------------------------------
// negA = -exp(A_log)
__global__ void k_negA(const float* __restrict__ A_log) {
    int i = blockIdx.x * blockDim.x + threadIdx.x;
    if (i < DI_ * DS_) g_negA[i] = -__expf(A_log[i]);
}

// ---------------------------------------------------------------------------
// in_proj: xz = hs @ W^T + b ; x_pre = xz[:,0:256], z = xz[:,256:512]
// 4 rows per block, 512 threads (one output column each)
__global__ void k_inproj(const float* __restrict__ hs,
                         const float* __restrict__ W,
                         const float* __restrict__ bias) {
    __shared__ float sh[4][DM_];
    int r0 = blockIdx.x * 4;
    int t  = threadIdx.x;            // 0..511
    {
        int r = t >> 7, k = t & 127;
        sh[r][k] = hs[(r0 + r) * DM_ + k];
    }
    __syncthreads();

    const float* wr = W + t * DM_;
    float a0 = 0.f, a1 = 0.f, a2 = 0.f, a3 = 0.f;
    #pragma unroll 8
    for (int k = 0; k < DM_; k++) {
        float wv = __ldg(wr + k);
        a0 = fmaf(wv, sh[0][k], a0);
        a1 = fmaf(wv, sh[1][k], a1);
        a2 = fmaf(wv, sh[2][k], a2);
        a3 = fmaf(wv, sh[3][k], a3);
    }
    float bv = __ldg(bias + t);
    a0 += bv; a1 += bv; a2 += bv; a3 += bv;
    if (t < DI_) {
        g_xpre[(r0 + 0) * DI_ + t] = a0;
        g_xpre[(r0 + 1) * DI_ + t] = a1;
        g_xpre[(r0 + 2) * DI_ + t] = a2;
        g_xpre[(r0 + 3) * DI_ + t] = a3;
    } else {
        int j = t - DI_;
        g_z[(r0 + 0) * DI_ + j] = a0;
        g_z[(r0 + 1) * DI_ + j] = a1;
        g_z[(r0 + 2) * DI_ + j] = a2;
        g_z[(r0 + 3) * DI_ + j] = a3;
    }
}

// ---------------------------------------------------------------------------
// causal depthwise conv (width 4) + bias + silu -> g_x
__global__ void k_conv(const float* __restrict__ cw,
                       const float* __restrict__ cb) {
    int bl = blockIdx.x;               // b*100 + l
    int c  = threadIdx.x;              // channel 0..255
    int b  = bl / L_;
    int l  = bl - b * L_;
    float acc = __ldg(cb + c);
    #pragma unroll
    for (int j = 0; j < 4; j++) {
        int ll = l - 3 + j;
        if (ll >= 0)
            acc = fmaf(__ldg(cw + c * 4 + j), g_xpre[(b * L_ + ll) * DI_ + c], acc);
    }
    float sg = 1.f / (1.f + __expf(-acc));
    g_x[bl * DI_ + c] = acc * sg;
}

// ---------------------------------------------------------------------------
// Bm = x @ x_proj_w[0:256]^T ; dt = softplus(x @ dt_proj_w^T + dt_b)
// 4 rows per block, 512 threads (cols 0..255 -> Bm, 256..511 -> dt)
__global__ void k_xprojdt(const float* __restrict__ xW,
                          const float* __restrict__ dtW,
                          const float* __restrict__ dtb) {
    __shared__ float sh[4][DI_];
    int r0 = blockIdx.x * 4;
    int t  = threadIdx.x;            // 0..511
    for (int i = t; i < 4 * DI_; i += 512)
        sh[i >> 8][i & 255] = g_x[(r0 + (i >> 8)) * DI_ + (i & 255)];
    __syncthreads();

    const float* wr = (t < DS_) ? (xW + t * DI_) : (dtW + (t - DS_) * DI_);
    float a0 = 0.f, a1 = 0.f, a2 = 0.f, a3 = 0.f;
    #pragma unroll 8
    for (int k = 0; k < DI_; k++) {
        float wv = __ldg(wr + k);
        a0 = fmaf(wv, sh[0][k], a0);
        a1 = fmaf(wv, sh[1][k], a1);
        a2 = fmaf(wv, sh[2][k], a2);
        a3 = fmaf(wv, sh[3][k], a3);
    }
    if (t < DS_) {
        g_Bm[(r0 + 0) * DS_ + t] = a0;
        g_Bm[(r0 + 1) * DS_ + t] = a1;
        g_Bm[(r0 + 2) * DS_ + t] = a2;
        g_Bm[(r0 + 3) * DS_ + t] = a3;
    } else {
        int j = t - DS_;
        float bv = __ldg(dtb + j);
        float v, sp;
        v = a0 + bv; sp = (v > 15.f) ? v : log1pf(__expf(v)); g_dt[(r0 + 0) * DI_ + j] = sp;
        v = a1 + bv; sp = (v > 15.f) ? v : log1pf(__expf(v)); g_dt[(r0 + 1) * DI_ + j] = sp;
        v = a2 + bv; sp = (v > 15.f) ? v : log1pf(__expf(v)); g_dt[(r0 + 2) * DI_ + j] = sp;
        v = a3 + bv; sp = (v > 15.f) ? v : log1pf(__expf(v)); g_dt[(r0 + 3) * DI_ + j] = sp;
    }
}

// ---------------------------------------------------------------------------
// main: one block per (b,l), 256 threads = one per n (d_state index).
//   as[d,n] = state[b,l,d,n] * exp(dt[b,l,d] * negA[d,n]) + dt[b,l,d]*Bm[b,l,n]
//   y[b,l,n] = sum_d as[d,n] * C[l,d,n]   (reduction over d_inner axis!)
// block order = l*4 + b so the 4 batches sharing C[l] run adjacently (L2 reuse)
__global__ void __launch_bounds__(256) k_main(
        const float* __restrict__ state,
        const float* __restrict__ C,
        const float* __restrict__ D1,
        float*       __restrict__ out_state) {
    int l = blockIdx.x >> 2;          // 0..99
    int b = blockIdx.x & 3;           // 0..3
    int blr = b * L_ + l;
    int n = threadIdx.x;              // 0..255

    __shared__ float sdt[DI_];
    sdt[n] = g_dt[blr * DI_ + n];
    __syncthreads();

    float bm = g_Bm[blr * DS_ + n];
    const float* srow = state + (size_t)blr * DI_ * DS_ + n;
    const float* crow = C + (size_t)l * DI_ * DS_ + n;
    const float* narow = g_negA + n;
    float*       orow = out_state + (size_t)blr * DI_ * DS_ + n;

    float acc = 0.f;
    #pragma unroll 4
    for (int d = 0; d < DI_; d++) {
        float dt = sdt[d];
        float s  = __ldg(srow + d * DS_);
        float na = __ldg(narow + d * DS_);
        float c  = __ldg(crow + d * DS_);
        float as = fmaf(s, __expf(dt * na), dt * bm);
        orow[d * DS_] = as;
        acc = fmaf(as, c, acc);
    }

    float xv = g_x[blr * DI_ + n];
    float zv = g_z[blr * DI_ + n];
    float y  = fmaf(__ldg(&D1[n]), xv, acc);
    float sg = 1.f / (1.f + __expf(-zv));
    g_y[blr * DI_ + n] = y * (zv * sg);
}

// ---------------------------------------------------------------------------
// out = y @ out_proj_w^T + b ; 4 rows per block, 128 threads (one col each)
__global__ void k_outproj(const float* __restrict__ W,
                          const float* __restrict__ bias,
                          float* __restrict__ out) {
    __shared__ float sh[4][DI_];
    int r0 = blockIdx.x * 4;
    int t  = threadIdx.x;            // 0..127
    for (int i = t; i < 4 * DI_; i += 128)
        sh[i >> 8][i & 255] = g_y[(r0 + (i >> 8)) * DI_ + (i & 255)];
    __syncthreads();

    const float* wr = W + t * DI_;
    float a0 = 0.f, a1 = 0.f, a2 = 0.f, a3 = 0.f;
    #pragma unroll 8
    for (int k = 0; k < DI_; k++) {
        float wv = __ldg(wr + k);
        a0 = fmaf(wv, sh[0][k], a0);
        a1 = fmaf(wv, sh[1][k], a1);
        a2 = fmaf(wv, sh[2][k], a2);
        a3 = fmaf(wv, sh[3][k], a3);
    }
    float bv = __ldg(bias + t);
    out[(r0 + 0) * DM_ + t] = a0 + bv;
    out[(r0 + 1) * DM_ + t] = a1 + bv;
    out[(r0 + 2) * DM_ + t] = a2 + bv;
    out[(r0 + 3) * DM_ + t] = a3 + bv;
}

// ---------------------------------------------------------------------------
extern "C" void kernel_launch(void* const* d_in, const int* in_sizes, int n_in,
                              void* d_out, int out_size) {
    const float* hs      = (const float*)d_in[0];   // (4,100,128)
    const float* state   = (const float*)d_in[1];   // (4,100,256,256)
    const float* inW     = (const float*)d_in[2];   // (512,128)
    const float* inB     = (const float*)d_in[3];   // (512,)
    const float* convW   = (const float*)d_in[4];   // (256,1,4)
    const float* convB   = (const float*)d_in[5];   // (256,)
    const float* xW      = (const float*)d_in[6];   // (512,256)
    const float* dtW     = (const float*)d_in[7];   // (256,256)
    const float* dtB     = (const float*)d_in[8];   // (256,)
    const float* A_log   = (const float*)d_in[9];   // (256,256)
    const float* D1      = (const float*)d_in[10];  // (256,)
    const float* Cp      = (const float*)d_in[11];  // (100,256,256)
    const float* outW    = (const float*)d_in[12];  // (128,256)
    const float* outB    = (const float*)d_in[13];  // (128,)

    float* out       = (float*)d_out;               // (4,100,128) first
    float* out_state = out + B_ * L_ * DM_;         // then (4,100,256,256)

    k_negA   <<<(DI_ * DS_ + 255) / 256, 256>>>(A_log);
    k_inproj <<<BL_ / 4, 512>>>(hs, inW, inB);
    k_conv   <<<BL_, DI_>>>(convW, convB);
    k_xprojdt<<<BL_ / 4, 512>>>(xW, dtW, dtB);
    k_main   <<<BL_, 256>>>(state, Cp, D1, out_state);
    k_outproj<<<BL_ / 4, 128>>>(outW, outB, out);
}

// round 3
// speedup vs baseline: 1.3703x; 1.3703x over previous
#include <cuda_runtime.h>

#define B_  4
#define L_  100
#define BL_ 400           // B*L
#define DM_ 128           // d_model
#define DI_ 256           // d_inner
#define DS_ 256           // d_state

// scratch (device globals; no allocations allowed)
__device__ float g_xpre[BL_ * DI_];
__device__ float g_x   [BL_ * DI_];
__device__ float g_z   [BL_ * DI_];
__device__ float g_Bm  [BL_ * DS_];
__device__ float g_dt  [BL_ * DI_];
__device__ float g_y   [BL_ * DI_];
__device__ float g_negA[DI_ * DS_];
// transposed weights: tW[k*N + n] = W[n*K + k]
__device__ float g_tinW [DM_ * 512];   // 128 x 512
__device__ float g_txW  [DI_ * DS_];   // 256 x 256 (first DS rows of x_proj_w)
__device__ float g_tdtW [DI_ * DI_];   // 256 x 256
__device__ float g_toutW[DI_ * DM_];   // 256 x 128

// ---------------------------------------------------------------------------
// negA = -exp(A_log)
__global__ void k_negA(const float* __restrict__ A_log) {
    int i = blockIdx.x * blockDim.x + threadIdx.x;
    if (i < DI_ * DS_) g_negA[i] = -__expf(A_log[i]);
}

// ---------------------------------------------------------------------------
// transpose all 4 weight matrices with 32x32 smem tiles.
// blockIdx.y selects matrix; blockIdx.x = flattened tile index.
__global__ void k_transpose(const float* __restrict__ inW,
                            const float* __restrict__ xW,
                            const float* __restrict__ dtW,
                            const float* __restrict__ outW) {
    __shared__ float tile[32][33];
    const float* src; float* dst; int R, Ccol;   // src is R x Ccol
    switch (blockIdx.y) {
        case 0: src = inW;  dst = g_tinW;  R = 512; Ccol = DM_; break;
        case 1: src = xW;   dst = g_txW;   R = DS_; Ccol = DI_; break;
        case 2: src = dtW;  dst = g_tdtW;  R = DI_; Ccol = DI_; break;
        default:src = outW; dst = g_toutW; R = DM_; Ccol = DI_; break;
    }
    int tilesX = Ccol >> 5;
    int tx = blockIdx.x % tilesX;       // tile col (over Ccol)
    int ty = blockIdx.x / tilesX;       // tile row (over R)
    if (ty >= (R >> 5)) return;
    int c = tx * 32 + threadIdx.x;
    int r = ty * 32 + threadIdx.y;
    #pragma unroll
    for (int j = 0; j < 32; j += 8)
        tile[threadIdx.y + j][threadIdx.x] = src[(r + j) * Ccol + c];
    __syncthreads();
    int oc = ty * 32 + threadIdx.x;     // output col (over R)
    int orow = tx * 32 + threadIdx.y;   // output row (over Ccol)
    #pragma unroll
    for (int j = 0; j < 32; j += 8)
        dst[(orow + j) * R + oc] = tile[threadIdx.x][threadIdx.y + j];
}

// ---------------------------------------------------------------------------
// in_proj: xz = hs @ W^T + b ; uses transposed weights (coalesced over t)
// 4 rows per block, 512 threads (one output column each)
__global__ void k_inproj(const float* __restrict__ hs,
                         const float* __restrict__ bias) {
    __shared__ float sh[4][DM_];
    int r0 = blockIdx.x * 4;
    int t  = threadIdx.x;            // 0..511
    {
        int r = t >> 7, k = t & 127;
        sh[r][k] = hs[(r0 + r) * DM_ + k];
    }
    __syncthreads();

    float a0 = 0.f, a1 = 0.f, a2 = 0.f, a3 = 0.f;
    #pragma unroll 8
    for (int k = 0; k < DM_; k++) {
        float wv = g_tinW[k * 512 + t];
        a0 = fmaf(wv, sh[0][k], a0);
        a1 = fmaf(wv, sh[1][k], a1);
        a2 = fmaf(wv, sh[2][k], a2);
        a3 = fmaf(wv, sh[3][k], a3);
    }
    float bv = __ldg(bias + t);
    a0 += bv; a1 += bv; a2 += bv; a3 += bv;
    if (t < DI_) {
        g_xpre[(r0 + 0) * DI_ + t] = a0;
        g_xpre[(r0 + 1) * DI_ + t] = a1;
        g_xpre[(r0 + 2) * DI_ + t] = a2;
        g_xpre[(r0 + 3) * DI_ + t] = a3;
    } else {
        int j = t - DI_;
        g_z[(r0 + 0) * DI_ + j] = a0;
        g_z[(r0 + 1) * DI_ + j] = a1;
        g_z[(r0 + 2) * DI_ + j] = a2;
        g_z[(r0 + 3) * DI_ + j] = a3;
    }
}

// ---------------------------------------------------------------------------
// causal depthwise conv (width 4) + bias + silu -> g_x
__global__ void k_conv(const float* __restrict__ cw,
                       const float* __restrict__ cb) {
    int bl = blockIdx.x;               // b*100 + l
    int c  = threadIdx.x;              // channel 0..255
    int b  = bl / L_;
    int l  = bl - b * L_;
    float acc = __ldg(cb + c);
    #pragma unroll
    for (int j = 0; j < 4; j++) {
        int ll = l - 3 + j;
        if (ll >= 0)
            acc = fmaf(__ldg(cw + c * 4 + j), g_xpre[(b * L_ + ll) * DI_ + c], acc);
    }
    float sg = 1.f / (1.f + __expf(-acc));
    g_x[bl * DI_ + c] = acc * sg;
}

// ---------------------------------------------------------------------------
// Bm = x @ x_proj_w[0:256]^T ; dt = softplus(x @ dt_proj_w^T + dt_b)
// 4 rows per block, 512 threads; transposed weights -> coalesced
__global__ void k_xprojdt(const float* __restrict__ dtb) {
    __shared__ float sh[4][DI_];
    int r0 = blockIdx.x * 4;
    int t  = threadIdx.x;            // 0..511
    for (int i = t; i < 4 * DI_; i += 512)
        sh[i >> 8][i & 255] = g_x[(r0 + (i >> 8)) * DI_ + (i & 255)];
    __syncthreads();

    const float* wr = (t < DS_) ? (g_txW + t) : (g_tdtW + (t - DS_));
    float a0 = 0.f, a1 = 0.f, a2 = 0.f, a3 = 0.f;
    #pragma unroll 8
    for (int k = 0; k < DI_; k++) {
        float wv = wr[k * DI_];
        a0 = fmaf(wv, sh[0][k], a0);
        a1 = fmaf(wv, sh[1][k], a1);
        a2 = fmaf(wv, sh[2][k], a2);
        a3 = fmaf(wv, sh[3][k], a3);
    }
    if (t < DS_) {
        g_Bm[(r0 + 0) * DS_ + t] = a0;
        g_Bm[(r0 + 1) * DS_ + t] = a1;
        g_Bm[(r0 + 2) * DS_ + t] = a2;
        g_Bm[(r0 + 3) * DS_ + t] = a3;
    } else {
        int j = t - DS_;
        float bv = __ldg(dtb + j);
        float v, sp;
        v = a0 + bv; sp = (v > 15.f) ? v : log1pf(__expf(v)); g_dt[(r0 + 0) * DI_ + j] = sp;
        v = a1 + bv; sp = (v > 15.f) ? v : log1pf(__expf(v)); g_dt[(r0 + 1) * DI_ + j] = sp;
        v = a2 + bv; sp = (v > 15.f) ? v : log1pf(__expf(v)); g_dt[(r0 + 2) * DI_ + j] = sp;
        v = a3 + bv; sp = (v > 15.f) ? v : log1pf(__expf(v)); g_dt[(r0 + 3) * DI_ + j] = sp;
    }
}

// ---------------------------------------------------------------------------
// main: one block per (b,l). 256 threads = 4 d-quarter groups x 64 float4 n-lanes.
//   as[d,n] = state[b,l,d,n]*exp(dt[d]*negA[d,n]) + dt[d]*Bm[n]
//   y[b,l,n] = sum_d as[d,n] * C[l,d,n]   (reduce over d)
// block order l*4+b so 4 batches sharing C[l] run adjacently (L2 reuse).
__global__ void __launch_bounds__(256) k_main(
        const float* __restrict__ state,
        const float* __restrict__ C,
        const float* __restrict__ D1,
        float*       __restrict__ out_state) {
    int l = blockIdx.x >> 2;          // 0..99
    int b = blockIdx.x & 3;           // 0..3
    int blr = b * L_ + l;
    int t  = threadIdx.x;             // 0..255
    int dq = t >> 6;                  // d-quarter 0..3
    int nq = t & 63;                  // float4 lane over n

    __shared__ float sdt[DI_];
    sdt[t] = g_dt[blr * DI_ + t];
    __syncthreads();

    float4 bm = ((const float4*)(g_Bm + (size_t)blr * DS_))[nq];

    size_t rowbase = (size_t)blr * DI_ * DS_;
    size_t crowbase = (size_t)l * DI_ * DS_;
    int d0 = dq * 64;

    float4 acc = make_float4(0.f, 0.f, 0.f, 0.f);
    #pragma unroll 4
    for (int dd = 0; dd < 64; dd++) {
        int d = d0 + dd;
        float dt = sdt[d];
        const float4* s4  = (const float4*)(state + rowbase + (size_t)d * DS_);
        const float4* c4  = (const float4*)(C + crowbase + (size_t)d * DS_);
        const float4* na4 = (const float4*)(g_negA + (size_t)d * DS_);
        float4*       o4  = (float4*)(out_state + rowbase + (size_t)d * DS_);
        float4 s  = __ldg(s4 + nq);
        float4 na = __ldg(na4 + nq);
        float4 c  = __ldg(c4 + nq);
        float4 as;
        as.x = fmaf(s.x, __expf(dt * na.x), dt * bm.x);
        as.y = fmaf(s.y, __expf(dt * na.y), dt * bm.y);
        as.z = fmaf(s.z, __expf(dt * na.z), dt * bm.z);
        as.w = fmaf(s.w, __expf(dt * na.w), dt * bm.w);
        o4[nq] = as;
        acc.x = fmaf(as.x, c.x, acc.x);
        acc.y = fmaf(as.y, c.y, acc.y);
        acc.z = fmaf(as.z, c.z, acc.z);
        acc.w = fmaf(as.w, c.w, acc.w);
    }

    __shared__ float4 racc[4][64];
    racc[dq][nq] = acc;
    __syncthreads();

    if (dq == 0) {
        float4 a0 = racc[0][nq], a1 = racc[1][nq],
               a2 = racc[2][nq], a3 = racc[3][nq];
        float4 tot;
        tot.x = (a0.x + a1.x) + (a2.x + a3.x);
        tot.y = (a0.y + a1.y) + (a2.y + a3.y);
        tot.z = (a0.z + a1.z) + (a2.z + a3.z);
        tot.w = (a0.w + a1.w) + (a2.w + a3.w);
        float4 xv = ((const float4*)(g_x + (size_t)blr * DI_))[nq];
        float4 zv = ((const float4*)(g_z + (size_t)blr * DI_))[nq];
        float4 dv = __ldg(((const float4*)D1) + nq);
        float4 y;
        y.x = fmaf(dv.x, xv.x, tot.x) * (zv.x / (1.f + __expf(-zv.x)));
        y.y = fmaf(dv.y, xv.y, tot.y) * (zv.y / (1.f + __expf(-zv.y)));
        y.z = fmaf(dv.z, xv.z, tot.z) * (zv.z / (1.f + __expf(-zv.z)));
        y.w = fmaf(dv.w, xv.w, tot.w) * (zv.w / (1.f + __expf(-zv.w)));
        ((float4*)(g_y + (size_t)blr * DI_))[nq] = y;
    }
}

// ---------------------------------------------------------------------------
// out = y @ out_proj_w^T + b ; 4 rows per block, 128 threads (one col each)
__global__ void k_outproj(const float* __restrict__ bias,
                          float* __restrict__ out) {
    __shared__ float sh[4][DI_];
    int r0 = blockIdx.x * 4;
    int t  = threadIdx.x;            // 0..127
    for (int i = t; i < 4 * DI_; i += 128)
        sh[i >> 8][i & 255] = g_y[(r0 + (i >> 8)) * DI_ + (i & 255)];
    __syncthreads();

    float a0 = 0.f, a1 = 0.f, a2 = 0.f, a3 = 0.f;
    #pragma unroll 8
    for (int k = 0; k < DI_; k++) {
        float wv = g_toutW[k * DM_ + t];
        a0 = fmaf(wv, sh[0][k], a0);
        a1 = fmaf(wv, sh[1][k], a1);
        a2 = fmaf(wv, sh[2][k], a2);
        a3 = fmaf(wv, sh[3][k], a3);
    }
    float bv = __ldg(bias + t);
    out[(r0 + 0) * DM_ + t] = a0 + bv;
    out[(r0 + 1) * DM_ + t] = a1 + bv;
    out[(r0 + 2) * DM_ + t] = a2 + bv;
    out[(r0 + 3) * DM_ + t] = a3 + bv;
}

// ---------------------------------------------------------------------------
extern "C" void kernel_launch(void* const* d_in, const int* in_sizes, int n_in,
                              void* d_out, int out_size) {
    const float* hs      = (const float*)d_in[0];   // (4,100,128)
    const float* state   = (const float*)d_in[1];   // (4,100,256,256)
    const float* inW     = (const float*)d_in[2];   // (512,128)
    const float* inB     = (const float*)d_in[3];   // (512,)
    const float* convW   = (const float*)d_in[4];   // (256,1,4)
    const float* convB   = (const float*)d_in[5];   // (256,)
    const float* xW      = (const float*)d_in[6];   // (512,256)
    const float* dtW     = (const float*)d_in[7];   // (256,256)
    const float* dtB     = (const float*)d_in[8];   // (256,)
    const float* A_log   = (const float*)d_in[9];   // (256,256)
    const float* D1      = (const float*)d_in[10];  // (256,)
    const float* Cp      = (const float*)d_in[11];  // (100,256,256)
    const float* outW    = (const float*)d_in[12];  // (128,256)
    const float* outB    = (const float*)d_in[13];  // (128,)

    float* out       = (float*)d_out;               // (4,100,128) first
    float* out_state = out + B_ * L_ * DM_;         // then (4,100,256,256)

    k_negA     <<<(DI_ * DS_ + 255) / 256, 256>>>(A_log);
    {
        dim3 grid(64, 4);               // max tiles per matrix = 64
        dim3 blk(32, 8);
        k_transpose<<<grid, blk>>>(inW, xW, dtW, outW);
    }
    k_inproj <<<BL_ / 4, 512>>>(hs, inB);
    k_conv   <<<BL_, DI_>>>(convW, convB);
    k_xprojdt<<<BL_ / 4, 512>>>(dtB);
    k_main   <<<BL_, 256>>>(state, Cp, D1, out_state);
    k_outproj<<<BL_ / 4, 128>>>(outB, out);
}

// round 4
// speedup vs baseline: 1.8173x; 1.3262x over previous
#include <cuda_runtime.h>

#define B_  4
#define L_  100
#define BL_ 400           // B*L
#define DM_ 128           // d_model
#define DI_ 256           // d_inner
#define DS_ 256           // d_state

// scratch (device globals; no allocations allowed)
__device__ float g_xpre[BL_ * DI_];
__device__ float g_x   [BL_ * DI_];
__device__ float g_z   [BL_ * DI_];
__device__ float g_Bm  [BL_ * DS_];
__device__ float g_dt  [BL_ * DI_];
__device__ float g_yp0 [BL_ * DS_];   // partial y, d-half 0
__device__ float g_yp1 [BL_ * DS_];   // partial y, d-half 1
__device__ float g_negA[DI_ * DS_];
// transposed weights: tW[k*N + n] = W[n*K + k]
__device__ float g_tinW [DM_ * 512];   // 128 x 512
__device__ float g_txW  [DI_ * DS_];   // 256 x 256 (first DS rows of x_proj_w)
__device__ float g_tdtW [DI_ * DI_];   // 256 x 256
__device__ float g_toutW[DI_ * DM_];   // 256 x 128

// ---------------------------------------------------------------------------
// negA = -exp(A_log)
__global__ void k_negA(const float* __restrict__ A_log) {
    int i = blockIdx.x * blockDim.x + threadIdx.x;
    if (i < DI_ * DS_) g_negA[i] = -__expf(A_log[i]);
}

// ---------------------------------------------------------------------------
// transpose all 4 weight matrices with 32x32 smem tiles.
__global__ void k_transpose(const float* __restrict__ inW,
                            const float* __restrict__ xW,
                            const float* __restrict__ dtW,
                            const float* __restrict__ outW) {
    __shared__ float tile[32][33];
    const float* src; float* dst; int R, Ccol;   // src is R x Ccol
    switch (blockIdx.y) {
        case 0: src = inW;  dst = g_tinW;  R = 512; Ccol = DM_; break;
        case 1: src = xW;   dst = g_txW;   R = DS_; Ccol = DI_; break;
        case 2: src = dtW;  dst = g_tdtW;  R = DI_; Ccol = DI_; break;
        default:src = outW; dst = g_toutW; R = DM_; Ccol = DI_; break;
    }
    int tilesX = Ccol >> 5;
    int tx = blockIdx.x % tilesX;
    int ty = blockIdx.x / tilesX;
    if (ty >= (R >> 5)) return;
    int c = tx * 32 + threadIdx.x;
    int r = ty * 32 + threadIdx.y;
    #pragma unroll
    for (int j = 0; j < 32; j += 8)
        tile[threadIdx.y + j][threadIdx.x] = src[(r + j) * Ccol + c];
    __syncthreads();
    int oc = ty * 32 + threadIdx.x;
    int orow = tx * 32 + threadIdx.y;
    #pragma unroll
    for (int j = 0; j < 32; j += 8)
        dst[(orow + j) * R + oc] = tile[threadIdx.x][threadIdx.y + j];
}

// ---------------------------------------------------------------------------
// in_proj: xz = hs @ W^T + b ; transposed weights -> coalesced
__global__ void k_inproj(const float* __restrict__ hs,
                         const float* __restrict__ bias) {
    __shared__ float sh[4][DM_];
    int r0 = blockIdx.x * 4;
    int t  = threadIdx.x;            // 0..511
    {
        int r = t >> 7, k = t & 127;
        sh[r][k] = hs[(r0 + r) * DM_ + k];
    }
    __syncthreads();

    float a0 = 0.f, a1 = 0.f, a2 = 0.f, a3 = 0.f;
    #pragma unroll 8
    for (int k = 0; k < DM_; k++) {
        float wv = g_tinW[k * 512 + t];
        a0 = fmaf(wv, sh[0][k], a0);
        a1 = fmaf(wv, sh[1][k], a1);
        a2 = fmaf(wv, sh[2][k], a2);
        a3 = fmaf(wv, sh[3][k], a3);
    }
    float bv = __ldg(bias + t);
    a0 += bv; a1 += bv; a2 += bv; a3 += bv;
    if (t < DI_) {
        g_xpre[(r0 + 0) * DI_ + t] = a0;
        g_xpre[(r0 + 1) * DI_ + t] = a1;
        g_xpre[(r0 + 2) * DI_ + t] = a2;
        g_xpre[(r0 + 3) * DI_ + t] = a3;
    } else {
        int j = t - DI_;
        g_z[(r0 + 0) * DI_ + j] = a0;
        g_z[(r0 + 1) * DI_ + j] = a1;
        g_z[(r0 + 2) * DI_ + j] = a2;
        g_z[(r0 + 3) * DI_ + j] = a3;
    }
}

// ---------------------------------------------------------------------------
// causal depthwise conv (width 4) + bias + silu -> g_x
__global__ void k_conv(const float* __restrict__ cw,
                       const float* __restrict__ cb) {
    int bl = blockIdx.x;               // b*100 + l
    int c  = threadIdx.x;              // channel 0..255
    int b  = bl / L_;
    int l  = bl - b * L_;
    float acc = __ldg(cb + c);
    #pragma unroll
    for (int j = 0; j < 4; j++) {
        int ll = l - 3 + j;
        if (ll >= 0)
            acc = fmaf(__ldg(cw + c * 4 + j), g_xpre[(b * L_ + ll) * DI_ + c], acc);
    }
    float sg = 1.f / (1.f + __expf(-acc));
    g_x[bl * DI_ + c] = acc * sg;
}

// ---------------------------------------------------------------------------
// Bm = x @ x_proj_w[0:256]^T ; dt = softplus(x @ dt_proj_w^T + dt_b)
__global__ void k_xprojdt(const float* __restrict__ dtb) {
    __shared__ float sh[4][DI_];
    int r0 = blockIdx.x * 4;
    int t  = threadIdx.x;            // 0..511
    for (int i = t; i < 4 * DI_; i += 512)
        sh[i >> 8][i & 255] = g_x[(r0 + (i >> 8)) * DI_ + (i & 255)];
    __syncthreads();

    const float* wr = (t < DS_) ? (g_txW + t) : (g_tdtW + (t - DS_));
    float a0 = 0.f, a1 = 0.f, a2 = 0.f, a3 = 0.f;
    #pragma unroll 8
    for (int k = 0; k < DI_; k++) {
        float wv = wr[k * DI_];
        a0 = fmaf(wv, sh[0][k], a0);
        a1 = fmaf(wv, sh[1][k], a1);
        a2 = fmaf(wv, sh[2][k], a2);
        a3 = fmaf(wv, sh[3][k], a3);
    }
    if (t < DS_) {
        g_Bm[(r0 + 0) * DS_ + t] = a0;
        g_Bm[(r0 + 1) * DS_ + t] = a1;
        g_Bm[(r0 + 2) * DS_ + t] = a2;
        g_Bm[(r0 + 3) * DS_ + t] = a3;
    } else {
        int j = t - DS_;
        float bv = __ldg(dtb + j);
        float v, sp;
        v = a0 + bv; sp = (v > 15.f) ? v : log1pf(__expf(v)); g_dt[(r0 + 0) * DI_ + j] = sp;
        v = a1 + bv; sp = (v > 15.f) ? v : log1pf(__expf(v)); g_dt[(r0 + 1) * DI_ + j] = sp;
        v = a2 + bv; sp = (v > 15.f) ? v : log1pf(__expf(v)); g_dt[(r0 + 2) * DI_ + j] = sp;
        v = a3 + bv; sp = (v > 15.f) ? v : log1pf(__expf(v)); g_dt[(r0 + 3) * DI_ + j] = sp;
    }
}

// ---------------------------------------------------------------------------
// main: 800 blocks = (l, half, b) with b fastest; 512 threads =
// 8 d-subgroups x 64 float4 n-lanes, 16 d's per subgroup.
//   as[d,n] = state[b,l,d,n]*exp(dt[d]*negA[d,n]) + dt[d]*Bm[n]
//   yp[h][b,l,n] = sum_{d in half h} as[d,n] * C[l,d,n]
// state: streaming loads/stores (__ldcs/__stcs); C/negA keep L2.
__global__ void __launch_bounds__(512) k_main(
        const float* __restrict__ state,
        const float* __restrict__ C,
        float*       __restrict__ out_state) {
    int bid = blockIdx.x;
    int b = bid & 3;
    int h = (bid >> 2) & 1;
    int l = bid >> 3;                 // 0..99
    int blr = b * L_ + l;
    int t  = threadIdx.x;             // 0..511
    int g  = t >> 6;                  // subgroup 0..7
    int nq = t & 63;                  // float4 lane over n

    __shared__ float sdt[128];        // dt for this half
    if (t < 128) sdt[t] = g_dt[blr * DI_ + h * 128 + t];
    __syncthreads();

    float4 bm = ((const float4*)(g_Bm + (size_t)blr * DS_))[nq];

    size_t rowbase  = (size_t)blr * DI_ * DS_;
    size_t crowbase = (size_t)l * DI_ * DS_;
    int d0 = h * 128 + g * 16;

    float4 acc = make_float4(0.f, 0.f, 0.f, 0.f);
    #pragma unroll 4
    for (int dd = 0; dd < 16; dd++) {
        int d = d0 + dd;
        const float4* s4  = (const float4*)(state + rowbase + (size_t)d * DS_);
        const float4* c4  = (const float4*)(C + crowbase + (size_t)d * DS_);
        const float4* na4 = (const float4*)(g_negA + (size_t)d * DS_);
        float4*       o4  = (float4*)(out_state + rowbase + (size_t)d * DS_);
        float  dt = sdt[d - h * 128];
        float4 s  = __ldcs(s4 + nq);
        float4 na = __ldg(na4 + nq);
        float4 c  = __ldg(c4 + nq);
        float4 as;
        as.x = fmaf(s.x, __expf(dt * na.x), dt * bm.x);
        as.y = fmaf(s.y, __expf(dt * na.y), dt * bm.y);
        as.z = fmaf(s.z, __expf(dt * na.z), dt * bm.z);
        as.w = fmaf(s.w, __expf(dt * na.w), dt * bm.w);
        __stcs(o4 + nq, as);
        acc.x = fmaf(as.x, c.x, acc.x);
        acc.y = fmaf(as.y, c.y, acc.y);
        acc.z = fmaf(as.z, c.z, acc.z);
        acc.w = fmaf(as.w, c.w, acc.w);
    }

    __shared__ float4 racc[8][64];
    racc[g][nq] = acc;
    __syncthreads();

    if (g == 0) {
        float4 tot = racc[0][nq];
        #pragma unroll
        for (int j = 1; j < 8; j++) {
            float4 a = racc[j][nq];
            tot.x += a.x; tot.y += a.y; tot.z += a.z; tot.w += a.w;
        }
        float* yp = h ? g_yp1 : g_yp0;
        ((float4*)(yp + (size_t)blr * DS_))[nq] = tot;
    }
}

// ---------------------------------------------------------------------------
// out = y @ out_proj_w^T + b with fused epilogue:
//   y[n] = (yp0[n]+yp1[n] + D1[n]*x[n]) * silu(z[n])
__global__ void k_outproj(const float* __restrict__ D1,
                          const float* __restrict__ bias,
                          float* __restrict__ out) {
    __shared__ float sh[4][DI_];
    int r0 = blockIdx.x * 4;
    int t  = threadIdx.x;            // 0..127
    for (int i = t; i < 4 * DI_; i += 128) {
        int r = i >> 8, k = i & 255;
        int idx = (r0 + r) * DI_ + k;
        float tot = g_yp0[idx] + g_yp1[idx];
        float xv = g_x[idx];
        float zv = g_z[idx];
        float y  = fmaf(__ldg(D1 + k), xv, tot);
        float sg = 1.f / (1.f + __expf(-zv));
        sh[r][k] = y * (zv * sg);
    }
    __syncthreads();

    float a0 = 0.f, a1 = 0.f, a2 = 0.f, a3 = 0.f;
    #pragma unroll 8
    for (int k = 0; k < DI_; k++) {
        float wv = g_toutW[k * DM_ + t];
        a0 = fmaf(wv, sh[0][k], a0);
        a1 = fmaf(wv, sh[1][k], a1);
        a2 = fmaf(wv, sh[2][k], a2);
        a3 = fmaf(wv, sh[3][k], a3);
    }
    float bv = __ldg(bias + t);
    out[(r0 + 0) * DM_ + t] = a0 + bv;
    out[(r0 + 1) * DM_ + t] = a1 + bv;
    out[(r0 + 2) * DM_ + t] = a2 + bv;
    out[(r0 + 3) * DM_ + t] = a3 + bv;
}

// ---------------------------------------------------------------------------
extern "C" void kernel_launch(void* const* d_in, const int* in_sizes, int n_in,
                              void* d_out, int out_size) {
    const float* hs      = (const float*)d_in[0];   // (4,100,128)
    const float* state   = (const float*)d_in[1];   // (4,100,256,256)
    const float* inW     = (const float*)d_in[2];   // (512,128)
    const float* inB     = (const float*)d_in[3];   // (512,)
    const float* convW   = (const float*)d_in[4];   // (256,1,4)
    const float* convB   = (const float*)d_in[5];   // (256,)
    const float* xW      = (const float*)d_in[6];   // (512,256)
    const float* dtW     = (const float*)d_in[7];   // (256,256)
    const float* dtB     = (const float*)d_in[8];   // (256,)
    const float* A_log   = (const float*)d_in[9];   // (256,256)
    const float* D1      = (const float*)d_in[10];  // (256,)
    const float* Cp      = (const float*)d_in[11];  // (100,256,256)
    const float* outW    = (const float*)d_in[12];  // (128,256)
    const float* outB    = (const float*)d_in[13];  // (128,)

    float* out       = (float*)d_out;               // (4,100,128) first
    float* out_state = out + B_ * L_ * DM_;         // then (4,100,256,256)

    k_negA     <<<(DI_ * DS_ + 255) / 256, 256>>>(A_log);
    {
        dim3 grid(64, 4);
        dim3 blk(32, 8);
        k_transpose<<<grid, blk>>>(inW, xW, dtW, outW);
    }
    k_inproj <<<BL_ / 4, 512>>>(hs, inB);
    k_conv   <<<BL_, DI_>>>(convW, convB);
    k_xprojdt<<<BL_ / 4, 512>>>(dtB);
    k_main   <<<BL_ * 2, 512>>>(state, Cp, out_state);
    k_outproj<<<BL_ / 4, 128>>>(D1, outB, out);
}

// round 5
// speedup vs baseline: 1.8933x; 1.0419x over previous
#include <cuda_runtime.h>

#define B_  4
#define L_  100
#define BL_ 400           // B*L
#define DM_ 128           // d_model
#define DI_ 256           // d_inner
#define DS_ 256           // d_state

// scratch (device globals; no allocations allowed)
__device__ float g_xpre[BL_ * DI_];
__device__ float g_x   [BL_ * DI_];
__device__ float g_z   [BL_ * DI_];
__device__ float g_Bm  [BL_ * DS_];
__device__ float g_dt  [BL_ * DI_];
__device__ float g_yp0 [BL_ * DS_];   // partial y, d-quarter 0
__device__ float g_yp1 [BL_ * DS_];
__device__ float g_yp2 [BL_ * DS_];
__device__ float g_yp3 [BL_ * DS_];
__device__ float g_negA[DI_ * DS_];
// transposed weights: tW[k*N + n] = W[n*K + k]
__device__ float g_tinW [DM_ * 512];   // 128 x 512
__device__ float g_txW  [DI_ * DS_];   // 256 x 256 (first DS rows of x_proj_w)
__device__ float g_tdtW [DI_ * DI_];   // 256 x 256
__device__ float g_toutW[DI_ * DM_];   // 256 x 128

// ---------------------------------------------------------------------------
// prep: blockIdx.y 0..3 -> transpose one weight matrix; y==4 -> negA
__global__ void k_prep(const float* __restrict__ inW,
                       const float* __restrict__ xW,
                       const float* __restrict__ dtW,
                       const float* __restrict__ outW,
                       const float* __restrict__ A_log) {
    if (blockIdx.y == 4) {
        int tid = threadIdx.y * 32 + threadIdx.x;       // 0..255
        for (int i = blockIdx.x * 256 + tid; i < DI_ * DS_; i += 64 * 256)
            g_negA[i] = -__expf(A_log[i]);
        return;
    }
    __shared__ float tile[32][33];
    const float* src; float* dst; int R, Ccol;   // src is R x Ccol
    switch (blockIdx.y) {
        case 0: src = inW;  dst = g_tinW;  R = 512; Ccol = DM_; break;
        case 1: src = xW;   dst = g_txW;   R = DS_; Ccol = DI_; break;
        case 2: src = dtW;  dst = g_tdtW;  R = DI_; Ccol = DI_; break;
        default:src = outW; dst = g_toutW; R = DM_; Ccol = DI_; break;
    }
    int tilesX = Ccol >> 5;
    int tx = blockIdx.x % tilesX;
    int ty = blockIdx.x / tilesX;
    if (ty >= (R >> 5)) return;
    int c = tx * 32 + threadIdx.x;
    int r = ty * 32 + threadIdx.y;
    #pragma unroll
    for (int j = 0; j < 32; j += 8)
        tile[threadIdx.y + j][threadIdx.x] = src[(r + j) * Ccol + c];
    __syncthreads();
    int oc = ty * 32 + threadIdx.x;
    int orow = tx * 32 + threadIdx.y;
    #pragma unroll
    for (int j = 0; j < 32; j += 8)
        dst[(orow + j) * R + oc] = tile[threadIdx.x][threadIdx.y + j];
}

// ---------------------------------------------------------------------------
// in_proj: xz = hs @ W^T + b ; transposed weights -> coalesced
__global__ void k_inproj(const float* __restrict__ hs,
                         const float* __restrict__ bias) {
    __shared__ float sh[4][DM_];
    int r0 = blockIdx.x * 4;
    int t  = threadIdx.x;            // 0..511
    {
        int r = t >> 7, k = t & 127;
        sh[r][k] = hs[(r0 + r) * DM_ + k];
    }
    __syncthreads();

    float a0 = 0.f, a1 = 0.f, a2 = 0.f, a3 = 0.f;
    #pragma unroll 8
    for (int k = 0; k < DM_; k++) {
        float wv = g_tinW[k * 512 + t];
        a0 = fmaf(wv, sh[0][k], a0);
        a1 = fmaf(wv, sh[1][k], a1);
        a2 = fmaf(wv, sh[2][k], a2);
        a3 = fmaf(wv, sh[3][k], a3);
    }
    float bv = __ldg(bias + t);
    a0 += bv; a1 += bv; a2 += bv; a3 += bv;
    if (t < DI_) {
        g_xpre[(r0 + 0) * DI_ + t] = a0;
        g_xpre[(r0 + 1) * DI_ + t] = a1;
        g_xpre[(r0 + 2) * DI_ + t] = a2;
        g_xpre[(r0 + 3) * DI_ + t] = a3;
    } else {
        int j = t - DI_;
        g_z[(r0 + 0) * DI_ + j] = a0;
        g_z[(r0 + 1) * DI_ + j] = a1;
        g_z[(r0 + 2) * DI_ + j] = a2;
        g_z[(r0 + 3) * DI_ + j] = a3;
    }
}

// ---------------------------------------------------------------------------
// fused: causal depthwise conv(4)+silu for 4 rows, then
// Bm = x @ x_proj_w[0:256]^T ; dt = softplus(x @ dt_proj_w^T + dt_b)
// blocks of 4 rows stay within one batch (100 % 4 == 0).
__global__ void k_convxproj(const float* __restrict__ cw,
                            const float* __restrict__ cb,
                            const float* __restrict__ dtb) {
    __shared__ float sh[4][DI_];
    int r0 = blockIdx.x * 4;
    int b  = r0 / L_;
    int l0 = r0 - b * L_;
    int t  = threadIdx.x;            // 0..511

    // conv + silu for the 4 rows (1024 items, 2 per thread)
    #pragma unroll
    for (int i = t; i < 4 * DI_; i += 512) {
        int r = i >> 8, c = i & 255;
        int l = l0 + r;
        float acc = __ldg(cb + c);
        #pragma unroll
        for (int j = 0; j < 4; j++) {
            int ll = l - 3 + j;
            if (ll >= 0)
                acc = fmaf(__ldg(cw + c * 4 + j), g_xpre[(b * L_ + ll) * DI_ + c], acc);
        }
        float sg = 1.f / (1.f + __expf(-acc));
        float xv = acc * sg;
        sh[r][c] = xv;
        g_x[(r0 + r) * DI_ + c] = xv;
    }
    __syncthreads();

    const float* wr = (t < DS_) ? (g_txW + t) : (g_tdtW + (t - DS_));
    float a0 = 0.f, a1 = 0.f, a2 = 0.f, a3 = 0.f;
    #pragma unroll 8
    for (int k = 0; k < DI_; k++) {
        float wv = wr[k * DI_];
        a0 = fmaf(wv, sh[0][k], a0);
        a1 = fmaf(wv, sh[1][k], a1);
        a2 = fmaf(wv, sh[2][k], a2);
        a3 = fmaf(wv, sh[3][k], a3);
    }
    if (t < DS_) {
        g_Bm[(r0 + 0) * DS_ + t] = a0;
        g_Bm[(r0 + 1) * DS_ + t] = a1;
        g_Bm[(r0 + 2) * DS_ + t] = a2;
        g_Bm[(r0 + 3) * DS_ + t] = a3;
    } else {
        int j = t - DS_;
        float bv = __ldg(dtb + j);
        float v, sp;
        v = a0 + bv; sp = (v > 15.f) ? v : log1pf(__expf(v)); g_dt[(r0 + 0) * DI_ + j] = sp;
        v = a1 + bv; sp = (v > 15.f) ? v : log1pf(__expf(v)); g_dt[(r0 + 1) * DI_ + j] = sp;
        v = a2 + bv; sp = (v > 15.f) ? v : log1pf(__expf(v)); g_dt[(r0 + 2) * DI_ + j] = sp;
        v = a3 + bv; sp = (v > 15.f) ? v : log1pf(__expf(v)); g_dt[(r0 + 3) * DI_ + j] = sp;
    }
}

// ---------------------------------------------------------------------------
// main: 1600 blocks = (l, quarter, b) with b fastest; 256 threads =
// 4 d-subgroups x 64 float4 n-lanes, 16 d's per subgroup (64 d per block).
//   as[d,n] = state[b,l,d,n]*exp(dt[d]*negA[d,n]) + dt[d]*Bm[n]
//   yp[q][b,l,n] = sum_{d in quarter q} as[d,n] * C[l,d,n]
__global__ void __launch_bounds__(256, 5) k_main(
        const float* __restrict__ state,
        const float* __restrict__ C,
        float*       __restrict__ out_state) {
    int bid = blockIdx.x;
    int b = bid & 3;
    int q = (bid >> 2) & 3;
    int l = bid >> 4;                 // 0..99
    int blr = b * L_ + l;
    int t  = threadIdx.x;             // 0..255
    int g  = t >> 6;                  // subgroup 0..3
    int nq = t & 63;                  // float4 lane over n

    __shared__ float sdt[64];         // dt for this quarter
    if (t < 64) sdt[t] = g_dt[blr * DI_ + q * 64 + t];
    __syncthreads();

    float4 bm = ((const float4*)(g_Bm + (size_t)blr * DS_))[nq];

    size_t rowbase  = (size_t)blr * DI_ * DS_;
    size_t crowbase = (size_t)l * DI_ * DS_;
    int d0 = q * 64 + g * 16;

    float4 acc = make_float4(0.f, 0.f, 0.f, 0.f);
    #pragma unroll 2
    for (int dd = 0; dd < 16; dd++) {
        int d = d0 + dd;
        const float4* s4  = (const float4*)(state + rowbase + (size_t)d * DS_);
        const float4* c4  = (const float4*)(C + crowbase + (size_t)d * DS_);
        const float4* na4 = (const float4*)(g_negA + (size_t)d * DS_);
        float4*       o4  = (float4*)(out_state + rowbase + (size_t)d * DS_);
        float  dt = sdt[d - q * 64];
        float4 s  = __ldcs(s4 + nq);
        float4 na = __ldg(na4 + nq);
        float4 c  = __ldg(c4 + nq);
        float4 as;
        as.x = fmaf(s.x, __expf(dt * na.x), dt * bm.x);
        as.y = fmaf(s.y, __expf(dt * na.y), dt * bm.y);
        as.z = fmaf(s.z, __expf(dt * na.z), dt * bm.z);
        as.w = fmaf(s.w, __expf(dt * na.w), dt * bm.w);
        __stcs(o4 + nq, as);
        acc.x = fmaf(as.x, c.x, acc.x);
        acc.y = fmaf(as.y, c.y, acc.y);
        acc.z = fmaf(as.z, c.z, acc.z);
        acc.w = fmaf(as.w, c.w, acc.w);
    }

    __shared__ float4 racc[4][64];
    racc[g][nq] = acc;
    __syncthreads();

    if (g == 0) {
        float4 a0 = racc[0][nq], a1 = racc[1][nq],
               a2 = racc[2][nq], a3 = racc[3][nq];
        float4 tot;
        tot.x = (a0.x + a1.x) + (a2.x + a3.x);
        tot.y = (a0.y + a1.y) + (a2.y + a3.y);
        tot.z = (a0.z + a1.z) + (a2.z + a3.z);
        tot.w = (a0.w + a1.w) + (a2.w + a3.w);
        float* yp = (q == 0) ? g_yp0 : (q == 1) ? g_yp1 : (q == 2) ? g_yp2 : g_yp3;
        ((float4*)(yp + (size_t)blr * DS_))[nq] = tot;
    }
}

// ---------------------------------------------------------------------------
// out = y @ out_proj_w^T + b with fused epilogue:
//   y[n] = (sum_q yp_q[n] + D1[n]*x[n]) * silu(z[n])
__global__ void k_outproj(const float* __restrict__ D1,
                          const float* __restrict__ bias,
                          float* __restrict__ out) {
    __shared__ float sh[4][DI_];
    int r0 = blockIdx.x * 4;
    int t  = threadIdx.x;            // 0..127
    for (int i = t; i < 4 * DI_; i += 128) {
        int r = i >> 8, k = i & 255;
        int idx = (r0 + r) * DI_ + k;
        float tot = (g_yp0[idx] + g_yp1[idx]) + (g_yp2[idx] + g_yp3[idx]);
        float xv = g_x[idx];
        float zv = g_z[idx];
        float y  = fmaf(__ldg(D1 + k), xv, tot);
        float sg = 1.f / (1.f + __expf(-zv));
        sh[r][k] = y * (zv * sg);
    }
    __syncthreads();

    float a0 = 0.f, a1 = 0.f, a2 = 0.f, a3 = 0.f;
    #pragma unroll 8
    for (int k = 0; k < DI_; k++) {
        float wv = g_toutW[k * DM_ + t];
        a0 = fmaf(wv, sh[0][k], a0);
        a1 = fmaf(wv, sh[1][k], a1);
        a2 = fmaf(wv, sh[2][k], a2);
        a3 = fmaf(wv, sh[3][k], a3);
    }
    float bv = __ldg(bias + t);
    out[(r0 + 0) * DM_ + t] = a0 + bv;
    out[(r0 + 1) * DM_ + t] = a1 + bv;
    out[(r0 + 2) * DM_ + t] = a2 + bv;
    out[(r0 + 3) * DM_ + t] = a3 + bv;
}

// ---------------------------------------------------------------------------
extern "C" void kernel_launch(void* const* d_in, const int* in_sizes, int n_in,
                              void* d_out, int out_size) {
    const float* hs      = (const float*)d_in[0];   // (4,100,128)
    const float* state   = (const float*)d_in[1];   // (4,100,256,256)
    const float* inW     = (const float*)d_in[2];   // (512,128)
    const float* inB     = (const float*)d_in[3];   // (512,)
    const float* convW   = (const float*)d_in[4];   // (256,1,4)
    const float* convB   = (const float*)d_in[5];   // (256,)
    const float* xW      = (const float*)d_in[6];   // (512,256)
    const float* dtW     = (const float*)d_in[7];   // (256,256)
    const float* dtB     = (const float*)d_in[8];   // (256,)
    const float* A_log   = (const float*)d_in[9];   // (256,256)
    const float* D1      = (const float*)d_in[10];  // (256,)
    const float* Cp      = (const float*)d_in[11];  // (100,256,256)
    const float* outW    = (const float*)d_in[12];  // (128,256)
    const float* outB    = (const float*)d_in[13];  // (128,)

    float* out       = (float*)d_out;               // (4,100,128) first
    float* out_state = out + B_ * L_ * DM_;         // then (4,100,256,256)

    {
        dim3 grid(64, 5);
        dim3 blk(32, 8);
        k_prep<<<grid, blk>>>(inW, xW, dtW, outW, A_log);
    }
    k_inproj   <<<BL_ / 4, 512>>>(hs, inB);
    k_convxproj<<<BL_ / 4, 512>>>(convW, convB, dtB);
    k_main     <<<BL_ * 4, 256>>>(state, Cp, out_state);
    k_outproj  <<<BL_ / 4, 128>>>(D1, outB, out);
}

// round 6
// speedup vs baseline: 2.2298x; 1.1777x over previous
#include <cuda_runtime.h>

#define B_  4
#define L_  100
#define BL_ 400           // B*L
#define DM_ 128           // d_model
#define DI_ 256           // d_inner
#define DS_ 256           // d_state
#define NQD 16            // d-chunks in k_main (16 d's each)

// scratch (device globals; no allocations allowed)
__device__ float g_xpre[BL_ * DI_];
__device__ float g_x   [BL_ * DI_];
__device__ float g_z   [BL_ * DI_];
__device__ float g_Bm  [BL_ * DS_];
__device__ float g_dt  [BL_ * DI_];
__device__ float g_ypart[NQD * BL_ * DS_];  // partial y per d-chunk
__device__ float g_negA[DI_ * DS_];
// transposed weights: tW[k*N + n] = W[n*K + k]
__device__ float g_tinW [DM_ * 512];   // 128 x 512
__device__ float g_txW  [DI_ * DS_];   // 256 x 256 (first DS rows of x_proj_w)
__device__ float g_tdtW [DI_ * DI_];   // 256 x 256
__device__ float g_toutW[DI_ * DM_];   // 256 x 128

// ---------------------------------------------------------------------------
// prep: blockIdx.y 0..3 -> transpose one weight matrix; y==4 -> negA
__global__ void k_prep(const float* __restrict__ inW,
                       const float* __restrict__ xW,
                       const float* __restrict__ dtW,
                       const float* __restrict__ outW,
                       const float* __restrict__ A_log) {
    if (blockIdx.y == 4) {
        int tid = threadIdx.y * 32 + threadIdx.x;       // 0..255
        for (int i = blockIdx.x * 256 + tid; i < DI_ * DS_; i += 64 * 256)
            g_negA[i] = -__expf(A_log[i]);
        return;
    }
    __shared__ float tile[32][33];
    const float* src; float* dst; int R, Ccol;   // src is R x Ccol
    switch (blockIdx.y) {
        case 0: src = inW;  dst = g_tinW;  R = 512; Ccol = DM_; break;
        case 1: src = xW;   dst = g_txW;   R = DS_; Ccol = DI_; break;
        case 2: src = dtW;  dst = g_tdtW;  R = DI_; Ccol = DI_; break;
        default:src = outW; dst = g_toutW; R = DM_; Ccol = DI_; break;
    }
    int tilesX = Ccol >> 5;
    int tx = blockIdx.x % tilesX;
    int ty = blockIdx.x / tilesX;
    if (ty >= (R >> 5)) return;
    int c = tx * 32 + threadIdx.x;
    int r = ty * 32 + threadIdx.y;
    #pragma unroll
    for (int j = 0; j < 32; j += 8)
        tile[threadIdx.y + j][threadIdx.x] = src[(r + j) * Ccol + c];
    __syncthreads();
    int oc = ty * 32 + threadIdx.x;
    int orow = tx * 32 + threadIdx.y;
    #pragma unroll
    for (int j = 0; j < 32; j += 8)
        dst[(orow + j) * R + oc] = tile[threadIdx.x][threadIdx.y + j];
}

// ---------------------------------------------------------------------------
// in_proj: xz = hs @ W^T + b ; transposed weights -> coalesced
__global__ void k_inproj(const float* __restrict__ hs,
                         const float* __restrict__ bias) {
    __shared__ float sh[4][DM_];
    int r0 = blockIdx.x * 4;
    int t  = threadIdx.x;            // 0..511
    {
        int r = t >> 7, k = t & 127;
        sh[r][k] = hs[(r0 + r) * DM_ + k];
    }
    __syncthreads();

    float a0 = 0.f, a1 = 0.f, a2 = 0.f, a3 = 0.f;
    #pragma unroll 16
    for (int k = 0; k < DM_; k++) {
        float wv = g_tinW[k * 512 + t];
        a0 = fmaf(wv, sh[0][k], a0);
        a1 = fmaf(wv, sh[1][k], a1);
        a2 = fmaf(wv, sh[2][k], a2);
        a3 = fmaf(wv, sh[3][k], a3);
    }
    float bv = __ldg(bias + t);
    a0 += bv; a1 += bv; a2 += bv; a3 += bv;
    if (t < DI_) {
        g_xpre[(r0 + 0) * DI_ + t] = a0;
        g_xpre[(r0 + 1) * DI_ + t] = a1;
        g_xpre[(r0 + 2) * DI_ + t] = a2;
        g_xpre[(r0 + 3) * DI_ + t] = a3;
    } else {
        int j = t - DI_;
        g_z[(r0 + 0) * DI_ + j] = a0;
        g_z[(r0 + 1) * DI_ + j] = a1;
        g_z[(r0 + 2) * DI_ + j] = a2;
        g_z[(r0 + 3) * DI_ + j] = a3;
    }
}

// ---------------------------------------------------------------------------
// fused: causal depthwise conv(4)+silu for 4 rows, then
// Bm = x @ x_proj_w[0:256]^T ; dt = softplus(x @ dt_proj_w^T + dt_b)
__global__ void k_convxproj(const float* __restrict__ cw,
                            const float* __restrict__ cb,
                            const float* __restrict__ dtb) {
    __shared__ float sh[4][DI_];
    int r0 = blockIdx.x * 4;
    int b  = r0 / L_;
    int l0 = r0 - b * L_;
    int t  = threadIdx.x;            // 0..511

    #pragma unroll
    for (int i = t; i < 4 * DI_; i += 512) {
        int r = i >> 8, c = i & 255;
        int l = l0 + r;
        float acc = __ldg(cb + c);
        #pragma unroll
        for (int j = 0; j < 4; j++) {
            int ll = l - 3 + j;
            if (ll >= 0)
                acc = fmaf(__ldg(cw + c * 4 + j), g_xpre[(b * L_ + ll) * DI_ + c], acc);
        }
        float sg = 1.f / (1.f + __expf(-acc));
        float xv = acc * sg;
        sh[r][c] = xv;
        g_x[(r0 + r) * DI_ + c] = xv;
    }
    __syncthreads();

    const float* wr = (t < DS_) ? (g_txW + t) : (g_tdtW + (t - DS_));
    float a0 = 0.f, a1 = 0.f, a2 = 0.f, a3 = 0.f;
    #pragma unroll 16
    for (int k = 0; k < DI_; k++) {
        float wv = wr[k * DI_];
        a0 = fmaf(wv, sh[0][k], a0);
        a1 = fmaf(wv, sh[1][k], a1);
        a2 = fmaf(wv, sh[2][k], a2);
        a3 = fmaf(wv, sh[3][k], a3);
    }
    if (t < DS_) {
        g_Bm[(r0 + 0) * DS_ + t] = a0;
        g_Bm[(r0 + 1) * DS_ + t] = a1;
        g_Bm[(r0 + 2) * DS_ + t] = a2;
        g_Bm[(r0 + 3) * DS_ + t] = a3;
    } else {
        int j = t - DS_;
        float bv = __ldg(dtb + j);
        float v, sp;
        v = a0 + bv; sp = (v > 15.f) ? v : log1pf(__expf(v)); g_dt[(r0 + 0) * DI_ + j] = sp;
        v = a1 + bv; sp = (v > 15.f) ? v : log1pf(__expf(v)); g_dt[(r0 + 1) * DI_ + j] = sp;
        v = a2 + bv; sp = (v > 15.f) ? v : log1pf(__expf(v)); g_dt[(r0 + 2) * DI_ + j] = sp;
        v = a3 + bv; sp = (v > 15.f) ? v : log1pf(__expf(v)); g_dt[(r0 + 3) * DI_ + j] = sp;
    }
}

// ---------------------------------------------------------------------------
// main: 6400 blocks = (l, qd, b) with b fastest; 256 threads =
// 4 d-subgroups x 64 float4 n-lanes, 4 d's per subgroup (16 d per block).
//   as[d,n] = state[b,l,d,n]*exp(dt[d]*negA[d,n]) + dt[d]*Bm[n]
//   ypart[qd][b,l,n] = sum_{d in chunk qd} as[d,n] * C[l,d,n]
__global__ void __launch_bounds__(256, 6) k_main(
        const float* __restrict__ state,
        const float* __restrict__ C,
        float*       __restrict__ out_state) {
    int bid = blockIdx.x;
    int b  = bid & 3;
    int qd = (bid >> 2) & (NQD - 1);
    int l  = bid >> 6;                // 0..99
    int blr = b * L_ + l;
    int t  = threadIdx.x;             // 0..255
    int g  = t >> 6;                  // subgroup 0..3
    int nq = t & 63;                  // float4 lane over n

    __shared__ float sdt[16];         // dt for this chunk
    if (t < 16) sdt[t] = g_dt[blr * DI_ + qd * 16 + t];
    __syncthreads();

    float4 bm = ((const float4*)(g_Bm + (size_t)blr * DS_))[nq];

    size_t rowbase  = (size_t)blr * DI_ * DS_;
    size_t crowbase = (size_t)l * DI_ * DS_;
    int d0 = qd * 16 + g * 4;

    float4 acc = make_float4(0.f, 0.f, 0.f, 0.f);
    #pragma unroll
    for (int dd = 0; dd < 4; dd++) {
        int d = d0 + dd;
        const float4* s4  = (const float4*)(state + rowbase + (size_t)d * DS_);
        const float4* c4  = (const float4*)(C + crowbase + (size_t)d * DS_);
        const float4* na4 = (const float4*)(g_negA + (size_t)d * DS_);
        float4*       o4  = (float4*)(out_state + rowbase + (size_t)d * DS_);
        float  dt = sdt[d - qd * 16];
        float4 s  = __ldcs(s4 + nq);
        float4 na = __ldg(na4 + nq);
        float4 c  = __ldg(c4 + nq);
        float4 as;
        as.x = fmaf(s.x, __expf(dt * na.x), dt * bm.x);
        as.y = fmaf(s.y, __expf(dt * na.y), dt * bm.y);
        as.z = fmaf(s.z, __expf(dt * na.z), dt * bm.z);
        as.w = fmaf(s.w, __expf(dt * na.w), dt * bm.w);
        __stcs(o4 + nq, as);
        acc.x = fmaf(as.x, c.x, acc.x);
        acc.y = fmaf(as.y, c.y, acc.y);
        acc.z = fmaf(as.z, c.z, acc.z);
        acc.w = fmaf(as.w, c.w, acc.w);
    }

    __shared__ float4 racc[4][64];
    racc[g][nq] = acc;
    __syncthreads();

    if (g == 0) {
        float4 a0 = racc[0][nq], a1 = racc[1][nq],
               a2 = racc[2][nq], a3 = racc[3][nq];
        float4 tot;
        tot.x = (a0.x + a1.x) + (a2.x + a3.x);
        tot.y = (a0.y + a1.y) + (a2.y + a3.y);
        tot.z = (a0.z + a1.z) + (a2.z + a3.z);
        tot.w = (a0.w + a1.w) + (a2.w + a3.w);
        ((float4*)(g_ypart + (size_t)qd * BL_ * DS_ + (size_t)blr * DS_))[nq] = tot;
    }
}

// ---------------------------------------------------------------------------
// out = y @ out_proj_w^T + b with fused epilogue:
//   y[n] = (sum_qd ypart[qd][n] + D1[n]*x[n]) * silu(z[n])
// 256 threads: col = t&127, k-half = t>>7; smem reduce across halves.
__global__ void k_outproj(const float* __restrict__ D1,
                          const float* __restrict__ bias,
                          float* __restrict__ out) {
    __shared__ float sh[4][DI_];
    __shared__ float spart[2][4][DM_];
    int r0 = blockIdx.x * 4;
    int t  = threadIdx.x;            // 0..255
    int col = t & 127;
    int kh  = t >> 7;

    for (int i = t; i < 4 * DI_; i += 256) {
        int r = i >> 8, k = i & 255;
        int idx = (r0 + r) * DI_ + k;
        float tot = 0.f;
        #pragma unroll
        for (int qq = 0; qq < NQD; qq++)
            tot += g_ypart[qq * (BL_ * DS_) + idx];
        float xv = g_x[idx];
        float zv = g_z[idx];
        float y  = fmaf(__ldg(D1 + k), xv, tot);
        float sg = 1.f / (1.f + __expf(-zv));
        sh[r][k] = y * (zv * sg);
    }
    __syncthreads();

    float a0 = 0.f, a1 = 0.f, a2 = 0.f, a3 = 0.f;
    int kbase = kh * 128;
    #pragma unroll 16
    for (int kk = 0; kk < 128; kk++) {
        int k = kbase + kk;
        float wv = g_toutW[k * DM_ + col];
        a0 = fmaf(wv, sh[0][k], a0);
        a1 = fmaf(wv, sh[1][k], a1);
        a2 = fmaf(wv, sh[2][k], a2);
        a3 = fmaf(wv, sh[3][k], a3);
    }
    spart[kh][0][col] = a0;
    spart[kh][1][col] = a1;
    spart[kh][2][col] = a2;
    spart[kh][3][col] = a3;
    __syncthreads();

    if (kh == 0) {
        float bv = __ldg(bias + col);
        out[(r0 + 0) * DM_ + col] = spart[0][0][col] + spart[1][0][col] + bv;
        out[(r0 + 1) * DM_ + col] = spart[0][1][col] + spart[1][1][col] + bv;
        out[(r0 + 2) * DM_ + col] = spart[0][2][col] + spart[1][2][col] + bv;
        out[(r0 + 3) * DM_ + col] = spart[0][3][col] + spart[1][3][col] + bv;
    }
}

// ---------------------------------------------------------------------------
extern "C" void kernel_launch(void* const* d_in, const int* in_sizes, int n_in,
                              void* d_out, int out_size) {
    const float* hs      = (const float*)d_in[0];   // (4,100,128)
    const float* state   = (const float*)d_in[1];   // (4,100,256,256)
    const float* inW     = (const float*)d_in[2];   // (512,128)
    const float* inB     = (const float*)d_in[3];   // (512,)
    const float* convW   = (const float*)d_in[4];   // (256,1,4)
    const float* convB   = (const float*)d_in[5];   // (256,)
    const float* xW      = (const float*)d_in[6];   // (512,256)
    const float* dtW     = (const float*)d_in[7];   // (256,256)
    const float* dtB     = (const float*)d_in[8];   // (256,)
    const float* A_log   = (const float*)d_in[9];   // (256,256)
    const float* D1      = (const float*)d_in[10];  // (256,)
    const float* Cp      = (const float*)d_in[11];  // (100,256,256)
    const float* outW    = (const float*)d_in[12];  // (128,256)
    const float* outB    = (const float*)d_in[13];  // (128,)

    float* out       = (float*)d_out;               // (4,100,128) first
    float* out_state = out + B_ * L_ * DM_;         // then (4,100,256,256)

    {
        dim3 grid(64, 5);
        dim3 blk(32, 8);
        k_prep<<<grid, blk>>>(inW, xW, dtW, outW, A_log);
    }
    k_inproj   <<<BL_ / 4, 512>>>(hs, inB);
    k_convxproj<<<BL_ / 4, 512>>>(convW, convB, dtB);
    k_main     <<<BL_ * NQD, 256>>>(state, Cp, out_state);   // 4th launch (profiled)
    k_outproj  <<<BL_ / 4, 256>>>(D1, outB, out);
}